// round 10
// baseline (speedup 1.0000x reference)
#include <cuda_runtime.h>
#include <cuda_bf16.h>
#include <cstdint>

#define NB 256

// Scratch: [b][mod][proj(Q,K,V)][640][100] fp32
__device__ float g_scr[196608000UL];
__device__ __nv_bfloat16 g_w_hi[6144000];
__device__ __nv_bfloat16 g_w_lo[6144000];
__device__ __nv_bfloat16 g_xt_hi[81920000UL];   // [b][l=100][c=3200]
__device__ __nv_bfloat16 g_xt_lo[81920000UL];

struct Params {
    const float* w[24];  // [mod][wq,wk,wv,bq,bk,bv]
};

// ---------------------------------------------------------------- helpers
__device__ __forceinline__ uint32_t smem_to_u32(const void* p) {
    uint32_t a;
    asm("{ .reg .u64 t; cvta.to.shared.u64 t, %1; cvt.u32.u64 %0, t; }" : "=r"(a) : "l"(p));
    return a;
}
__device__ __forceinline__ void ldsm4(uint32_t* r, uint32_t addr) {
    asm volatile("ldmatrix.sync.aligned.m8n8.x4.shared.b16 {%0,%1,%2,%3}, [%4];"
        : "=r"(r[0]), "=r"(r[1]), "=r"(r[2]), "=r"(r[3]) : "r"(addr));
}
__device__ __forceinline__ void ldsm2(uint32_t* r, uint32_t addr) {
    asm volatile("ldmatrix.sync.aligned.m8n8.x2.shared.b16 {%0,%1}, [%2];"
        : "=r"(r[0]), "=r"(r[1]) : "r"(addr));
}
__device__ __forceinline__ void mma16816(float* c, const uint32_t* a, uint32_t b0, uint32_t b1) {
    asm volatile("mma.sync.aligned.m16n8k16.row.col.f32.bf16.bf16.f32 "
        "{%0,%1,%2,%3}, {%4,%5,%6,%7}, {%8,%9}, {%0,%1,%2,%3};"
        : "+f"(c[0]), "+f"(c[1]), "+f"(c[2]), "+f"(c[3])
        : "r"(a[0]), "r"(a[1]), "r"(a[2]), "r"(a[3]), "r"(b0), "r"(b1));
}
__device__ __forceinline__ unsigned long long pack2(float x, float y) {
    unsigned long long r;
    asm("mov.b64 %0, {%1, %2};" : "=l"(r) : "f"(x), "f"(y));
    return r;
}
__device__ __forceinline__ void unpack2(unsigned long long v, float& x, float& y) {
    asm("mov.b64 {%0, %1}, %2;" : "=f"(x), "=f"(y) : "l"(v));
}
__device__ __forceinline__ void ffma2(unsigned long long& c, unsigned long long a, unsigned long long b) {
    asm("fma.rn.f32x2 %0, %1, %2, %0;" : "+l"(c) : "l"(a), "l"(b));
}
__device__ __forceinline__ unsigned long long lds_u64(uint32_t a) {
    unsigned long long v;
    asm volatile("ld.shared.b64 %0, [%1];" : "=l"(v) : "r"(a));
    return v;
}

// ============================================================================
// prep_w: fp32 weights -> bf16 hi/lo
// ============================================================================
__global__ void prep_w(Params p) {
    const int seg = blockIdx.y;
    const int mod = seg / 3;
    const int Cin = (mod == 1) ? 1280 : 640;
    const size_t offs[12] = {0, 409600, 819200, 1228800, 2048000, 2867200,
                             3686400, 4096000, 4505600, 4915200, 5324800, 5734400};
    const float* __restrict__ w = p.w[mod * 6 + (seg % 3)];
    const size_t off = offs[seg];
    const size_t n = (size_t)640 * Cin;
    for (size_t i = (size_t)blockIdx.x * blockDim.x + threadIdx.x; i < n; i += (size_t)gridDim.x * blockDim.x) {
        float v = w[i];
        __nv_bfloat16 h = __float2bfloat16(v);
        g_w_hi[off + i] = h;
        g_w_lo[off + i] = __float2bfloat16(v - __bfloat162float(h));
    }
}

// ============================================================================
// prep_x: x[b][C=3200][L=100] fp32 -> XT[b][l][c] bf16 hi/lo
// ============================================================================
__global__ void prep_x(const float* __restrict__ x) {
    __shared__ float t[32][33];
    const int b = blockIdx.z, ct = blockIdx.x, lt = blockIdx.y;
    const int tx = threadIdx.x, ty = threadIdx.y;
    const float* xb = x + (size_t)b * 320000;
    const int l = lt * 32 + tx;
    #pragma unroll
    for (int j = 0; j < 4; j++) {
        int c = ct * 32 + ty + j * 8;
        t[ty + j * 8][tx] = (l < 100) ? xb[(size_t)c * 100 + l] : 0.0f;
    }
    __syncthreads();
    const int c_out = ct * 32 + tx;
    const size_t xtb = (size_t)b * 320000;
    #pragma unroll
    for (int j = 0; j < 4; j++) {
        int lo_ = lt * 32 + ty + j * 8;
        if (lo_ < 100) {
            float v = t[tx][ty + j * 8];
            __nv_bfloat16 h = __float2bfloat16(v);
            size_t o = xtb + (size_t)lo_ * 3200 + c_out;
            g_xt_hi[o] = h;
            g_xt_lo[o] = __float2bfloat16(v - __bfloat162float(h));
        }
    }
}

// ============================================================================
// qkv_mma: Y[128,104] tile, bf16 3-term split via mma.sync.
// NEW: 4m x 2n warp grid — warps 0-3 cols 0..55 (7 tiles), warps 4-7 cols
// 56..103 (6 tiles).  Cuts smem fragment reads 1.4x; SMSPs stay balanced.
// ============================================================================
#define STAGE  37120u
#define OFF_AH 0u
#define OFF_AL 10240u
#define OFF_BH 20480u
#define OFF_BL 28800u

__global__ __launch_bounds__(256, 2) void qkv_mma(Params p) {
    extern __shared__ __align__(16) char smem_raw[];
    const uint32_t sb = smem_to_u32(smem_raw);

    const int tid = threadIdx.x;
    int bid = blockIdx.x;
    const int mtile = bid % 5; bid /= 5;
    const int proj  = bid % 3; bid /= 3;
    const int mod   = bid & 3;
    const int b     = bid >> 2;

    const int Cin = (mod == 1) ? 1280 : 640;
    const int nch = Cin >> 5;
    const int mbase = mtile * 128;

    const size_t offs[12] = {0, 409600, 819200, 1228800, 2048000, 2867200,
                             3686400, 4096000, 4505600, 4915200, 5324800, 5734400};
    const int c0m_tab[4] = {2560, 640, 1920, 0};
    const size_t woff = offs[mod * 3 + proj];
    const size_t xoff = (size_t)b * 320000 + c0m_tab[mod];
    const float* __restrict__ bias = p.w[mod * 6 + 3 + proj];
    float* __restrict__ O = g_scr + ((((size_t)b * 4 + mod) * 3 + proj) * 640 + mbase) * 100;

    const __nv_bfloat16* __restrict__ Wh = g_w_hi + woff;
    const __nv_bfloat16* __restrict__ Wl = g_w_lo + woff;
    const __nv_bfloat16* __restrict__ Xh = g_xt_hi + xoff;
    const __nv_bfloat16* __restrict__ Xl = g_xt_lo + xoff;

    // zero B pad rows 100..103 (both stages, hi+lo)
    for (int idx = tid; idx < 320; idx += 256) {
        int st = idx / 160, rest = idx % 160;
        int buf = rest / 80, r2 = rest % 80;
        uint32_t a = sb + (uint32_t)st * STAGE + (buf ? OFF_BL : OFF_BH)
                   + (uint32_t)(100 + r2 / 20) * 80 + (uint32_t)(r2 % 20) * 4;
        asm volatile("st.shared.b32 [%0], %1;" :: "r"(a), "r"(0) : "memory");
    }

    auto issue_chunk = [&](int st, int c) {
        const int k0 = c << 5;
        const uint32_t stg = sb + (uint32_t)st * STAGE;
        for (int idx = tid; idx < 1824; idx += 256) {
            const __nv_bfloat16* src;
            uint32_t dst;
            if (idx < 1024) {
                int buf = idx >> 9, r = (idx >> 2) & 127, seg = idx & 3;
                src = (buf ? Wl : Wh) + (size_t)(mbase + r) * Cin + k0 + seg * 8;
                dst = stg + (buf ? OFF_AL : OFF_AH) + (uint32_t)r * 80 + (uint32_t)seg * 16;
            } else {
                int j = idx - 1024;
                int n = j >> 3, rem = j & 7;
                int buf = rem >> 2, seg = rem & 3;
                src = (buf ? Xl : Xh) + (size_t)n * 3200 + k0 + seg * 8;
                dst = stg + (buf ? OFF_BL : OFF_BH) + (uint32_t)n * 80 + (uint32_t)seg * 16;
            }
            asm volatile("cp.async.cg.shared.global [%0], [%1], 16;" :: "r"(dst), "l"(src) : "memory");
        }
        asm volatile("cp.async.commit_group;" ::: "memory");
    };

    const int wid = tid >> 5, lane = tid & 31;
    const int wm = wid & 3;              // m block: rows wm*32 .. +31
    const int wn = wid >> 2;             // n block: cols wn*56 (7 or 6 tiles)
    const int ntiles = 7 - wn;           // wn0: 7, wn1: 6
    const int npairs = 3;
    const int qd = lane & 3;

    // A ldsm base: rows wm*32 + (lane&15), k-half select (lane>>4)
    const uint32_t aoff = (uint32_t)(wm * 32 + (lane & 15)) * 80 + (uint32_t)(lane >> 4) * 16;
    // B pair ldsm offsets (relative to pair base)
    const uint32_t b4off = (uint32_t)(((lane >> 4) * 8) + (lane & 7)) * 80 + (uint32_t)((lane >> 3) & 1) * 16;
    const uint32_t b2off = (uint32_t)(lane & 7) * 80 + (uint32_t)((lane >> 3) & 1) * 16;
    const uint32_t bbase = (uint32_t)(wn * 56) * 80;   // col region start

    float acc[2][7][4];
    #pragma unroll
    for (int mt = 0; mt < 2; mt++)
        #pragma unroll
        for (int t = 0; t < 7; t++)
            #pragma unroll
            for (int i = 0; i < 4; i++) acc[mt][t][i] = 0.0f;

    issue_chunk(0, 0);

    for (int c = 0; c < nch; c++) {
        const int s = c & 1;
        if (c + 1 < nch) {
            issue_chunk(s ^ 1, c + 1);
            asm volatile("cp.async.wait_group 1;" ::: "memory");
        } else {
            asm volatile("cp.async.wait_group 0;" ::: "memory");
        }
        __syncthreads();

        const uint32_t stg = sb + (uint32_t)s * STAGE;
        const uint32_t aAh = stg + OFF_AH + aoff;
        const uint32_t aAl = stg + OFF_AL + aoff;
        const uint32_t aBh = stg + OFF_BH + bbase;
        const uint32_t aBl = stg + OFF_BL + bbase;

        #pragma unroll
        for (int s16 = 0; s16 < 2; s16++) {
            const uint32_t ko = (uint32_t)s16 * 32;
            uint32_t ah[2][4], al[2][4];
            ldsm4(ah[0], aAh + ko);
            ldsm4(ah[1], aAh + 1280u + ko);
            ldsm4(al[0], aAl + ko);
            ldsm4(al[1], aAl + 1280u + ko);
            #pragma unroll
            for (int pr = 0; pr < npairs; pr++) {
                uint32_t bh[4], bl[4];
                ldsm4(bh, aBh + (uint32_t)pr * 1280u + b4off + ko);
                ldsm4(bl, aBl + (uint32_t)pr * 1280u + b4off + ko);
                #pragma unroll
                for (int mt = 0; mt < 2; mt++) {
                    mma16816(acc[mt][2 * pr],     ah[mt], bh[0], bh[1]);
                    mma16816(acc[mt][2 * pr + 1], ah[mt], bh[2], bh[3]);
                    mma16816(acc[mt][2 * pr],     ah[mt], bl[0], bl[1]);
                    mma16816(acc[mt][2 * pr + 1], ah[mt], bl[2], bl[3]);
                    mma16816(acc[mt][2 * pr],     al[mt], bh[0], bh[1]);
                    mma16816(acc[mt][2 * pr + 1], al[mt], bh[2], bh[3]);
                }
            }
            if (wn == 0) {   // 7th tile: cols 48..55
                uint32_t bh[2], bl[2];
                ldsm2(bh, aBh + 3840u + b2off + ko);
                ldsm2(bl, aBl + 3840u + b2off + ko);
                #pragma unroll
                for (int mt = 0; mt < 2; mt++) {
                    mma16816(acc[mt][6], ah[mt], bh[0], bh[1]);
                    mma16816(acc[mt][6], ah[mt], bl[0], bl[1]);
                    mma16816(acc[mt][6], al[mt], bh[0], bh[1]);
                }
            }
        }
        __syncthreads();
    }

    // epilogue
    #pragma unroll
    for (int mt = 0; mt < 2; mt++) {
        const int row0 = wm * 32 + mt * 16 + (lane >> 2);
        const float bv0 = bias[mbase + row0];
        const float bv1 = bias[mbase + row0 + 8];
        float* o0 = O + (size_t)row0 * 100;
        float* o1 = o0 + 800;
        #pragma unroll
        for (int t = 0; t < 7; t++) {
            if (t < ntiles) {
                int col = wn * 56 + t * 8 + qd * 2;
                if (col < 100) {
                    *(float2*)(o0 + col) = make_float2(acc[mt][t][0] + bv0, acc[mt][t][1] + bv0);
                    *(float2*)(o1 + col) = make_float2(acc[mt][t][2] + bv1, acc[mt][t][3] + bv1);
                }
            }
        }
    }
}

// ============================================================================
// Pass 2: attention v4 (unchanged from R9).
// ============================================================================
#define PT_OFF   0
#define U_OFF    10000
#define KC_OFF   3328
#define PART_OFF 16656
#define ROW_OFF  17656
#define ATTN_SMEM 71040

__global__ __launch_bounds__(256, 3) void attn_kernel(float* __restrict__ out) {
    extern __shared__ __align__(16) float sm[];
    const int tid = threadIdx.x;
    const int bm = blockIdx.x;
    const int mod = bm & 3, b = bm >> 2;

    const float* __restrict__ Q = g_scr + (size_t)bm * 192000;
    const float* __restrict__ K = Q + 64000;
    const float* __restrict__ V = Q + 128000;
    float* __restrict__ O = out + ((size_t)mod * NB + b) * 64000;

    float* Pt   = sm + PT_OFF;
    float* U    = sm + U_OFF;
    float* part = sm + PART_OFF;
    float* row  = sm + ROW_OFF;
    const uint32_t u_b = smem_to_u32(U);
    const uint32_t pt_b = smem_to_u32(Pt);

    const bool act = tid < 250;
    const int lg = tid % 25;
    const int mg = tid / 25;
    const int m0 = mg * 10;

    unsigned long long acc[4][5];
    #pragma unroll
    for (int t = 0; t < 4; t++)
        #pragma unroll
        for (int j = 0; j < 5; j++) acc[t][j] = 0ULL;

    for (int c0 = 0; c0 < 640; c0 += 32) {
        for (int idx = tid; idx < 1600; idx += 256) {
            int which = idx >= 800;
            int i2 = idx - which * 800;
            int rw = i2 / 25, c4 = (i2 % 25) * 4;
            const float* src = (which ? K : Q) + (size_t)(c0 + rw) * 100 + c4;
            *(float4*)(U + which * KC_OFF + rw * 104 + c4) = *(const float4*)src;
        }
        __syncthreads();
        if (act) {
            #pragma unroll 2
            for (int kk = 0; kk < 32; kk++) {
                const float* qrow = U + kk * 104;
                unsigned long long qd_[4];
                #pragma unroll
                for (int t = 0; t < 4; t++) {
                    float qv = qrow[lg + 25 * t];
                    qd_[t] = pack2(qv, qv);
                }
                const uint32_t kb = u_b + (uint32_t)(KC_OFF + kk * 104 + m0) * 4;
                #pragma unroll
                for (int j = 0; j < 5; j++) {
                    unsigned long long kv = lds_u64(kb + (uint32_t)j * 8);
                    ffma2(acc[0][j], qd_[0], kv);
                    ffma2(acc[1][j], qd_[1], kv);
                    ffma2(acc[2][j], qd_[2], kv);
                    ffma2(acc[3][j], qd_[3], kv);
                }
            }
        }
        __syncthreads();
    }

    if (act) {
        #pragma unroll
        for (int t = 0; t < 4; t++) {
            float mx = -3.4e38f;
            #pragma unroll
            for (int j = 0; j < 5; j++) {
                float lo, hi;
                unpack2(acc[t][j], lo, hi);
                mx = fmaxf(mx, fmaxf(lo, hi));
            }
            part[(lg + 25 * t) * 10 + mg] = mx;
        }
    }
    __syncthreads();
    if (tid < 100) {
        float m = -3.4e38f;
        #pragma unroll
        for (int g = 0; g < 10; g++) m = fmaxf(m, part[tid * 10 + g]);
        row[tid] = m;
    }
    __syncthreads();
    if (act) {
        #pragma unroll
        for (int t = 0; t < 4; t++) {
            float mr = row[lg + 25 * t];
            float s = 0.0f;
            #pragma unroll
            for (int j = 0; j < 5; j++) {
                float lo, hi;
                unpack2(acc[t][j], lo, hi);
                float e0 = __expf(lo - mr), e1 = __expf(hi - mr);
                s += e0 + e1;
                acc[t][j] = pack2(e0, e1);
            }
            part[(lg + 25 * t) * 10 + mg] = s;
        }
    }
    __syncthreads();
    if (tid < 100) {
        float s = 0.0f;
        #pragma unroll
        for (int g = 0; g < 10; g++) s += part[tid * 10 + g];
        row[tid] = 1.0f / s;
    }
    __syncthreads();
    if (act) {
        #pragma unroll
        for (int t = 0; t < 4; t++) {
            int l = lg + 25 * t;
            float inv = row[l];
            #pragma unroll
            for (int j = 0; j < 5; j++) {
                float lo, hi;
                unpack2(acc[t][j], lo, hi);
                int m = m0 + 2 * j;
                Pt[m * 100 + l]       = lo * inv;
                Pt[(m + 1) * 100 + l] = hi * inv;
            }
        }
    }

    const int cgC = tid % 16, igC = tid / 16;
    const bool actC = igC < 10;
    const int i0 = igC * 10;

    for (int chunk = 0; chunk < 10; chunk++) {
        __syncthreads();
        for (int idx = tid; idx < 1600; idx += 256) {
            int rw = idx / 25, c4 = (idx % 25) * 4;
            *(float4*)(U + rw * 100 + c4) =
                *(const float4*)(V + (size_t)(chunk * 64 + rw) * 100 + c4);
        }
        __syncthreads();
        if (actC) {
            unsigned long long pacc[4][5];
            #pragma unroll
            for (int u = 0; u < 4; u++)
                #pragma unroll
                for (int s = 0; s < 5; s++) pacc[u][s] = 0ULL;
            const uint32_t pb = pt_b + (uint32_t)i0 * 4;
            #pragma unroll 4
            for (int j = 0; j < 100; j++) {
                unsigned long long vd[4];
                #pragma unroll
                for (int u = 0; u < 4; u++) {
                    float vv = U[(cgC + 16 * u) * 100 + j];
                    vd[u] = pack2(vv, vv);
                }
                const uint32_t pj = pb + (uint32_t)j * 400;
                #pragma unroll
                for (int s = 0; s < 5; s++) {
                    unsigned long long pp = lds_u64(pj + (uint32_t)s * 8);
                    ffma2(pacc[0][s], vd[0], pp);
                    ffma2(pacc[1][s], vd[1], pp);
                    ffma2(pacc[2][s], vd[2], pp);
                    ffma2(pacc[3][s], vd[3], pp);
                }
            }
            #pragma unroll
            for (int u = 0; u < 4; u++) {
                int c_ = chunk * 64 + cgC + 16 * u;
                float* orow = O + (size_t)c_ * 100 + i0;
                #pragma unroll
                for (int s = 0; s < 5; s++) {
                    float a0, a1;
                    unpack2(pacc[u][s], a0, a1);
                    *(float2*)(orow + 2 * s) = make_float2(a0, a1);
                }
            }
        }
    }
}

extern "C" void kernel_launch(void* const* d_in, const int* in_sizes, int n_in,
                              void* d_out, int out_size) {
    const float* x = (const float*)d_in[0];
    Params p;
    for (int i = 0; i < 24; i++) p.w[i] = (const float*)d_in[1 + i];

    prep_w<<<dim3(800, 12), 256>>>(p);
    prep_x<<<dim3(100, 4, 256), dim3(32, 8)>>>(x);

    cudaFuncSetAttribute(qkv_mma, cudaFuncAttributeMaxDynamicSharedMemorySize, 74240);
    qkv_mma<<<15360, 256, 74240>>>(p);

    cudaFuncSetAttribute(attn_kernel, cudaFuncAttributeMaxDynamicSharedMemorySize, ATTN_SMEM);
    attn_kernel<<<1024, 256, ATTN_SMEM>>>((float*)d_out);
}

// round 11
// speedup vs baseline: 1.0398x; 1.0398x over previous
#include <cuda_runtime.h>
#include <cuda_bf16.h>
#include <cstdint>

#define NB 256

// Scratch: [b][mod][proj(Q,K,V)][640][100] fp32
__device__ float g_scr[196608000UL];
__device__ __nv_bfloat16 g_w_hi[6144000];
__device__ __nv_bfloat16 g_w_lo[6144000];
__device__ __nv_bfloat16 g_xt_hi[81920000UL];   // [b][l=100][c=3200]
__device__ __nv_bfloat16 g_xt_lo[81920000UL];

struct Params {
    const float* w[24];  // [mod][wq,wk,wv,bq,bk,bv]
};

// ---------------------------------------------------------------- helpers
__device__ __forceinline__ uint32_t smem_to_u32(const void* p) {
    uint32_t a;
    asm("{ .reg .u64 t; cvta.to.shared.u64 t, %1; cvt.u32.u64 %0, t; }" : "=r"(a) : "l"(p));
    return a;
}
__device__ __forceinline__ void ldsm4(uint32_t* r, uint32_t addr) {
    asm volatile("ldmatrix.sync.aligned.m8n8.x4.shared.b16 {%0,%1,%2,%3}, [%4];"
        : "=r"(r[0]), "=r"(r[1]), "=r"(r[2]), "=r"(r[3]) : "r"(addr));
}
__device__ __forceinline__ void ldsm2(uint32_t* r, uint32_t addr) {
    asm volatile("ldmatrix.sync.aligned.m8n8.x2.shared.b16 {%0,%1}, [%2];"
        : "=r"(r[0]), "=r"(r[1]) : "r"(addr));
}
__device__ __forceinline__ void mma16816(float* c, const uint32_t* a, uint32_t b0, uint32_t b1) {
    asm volatile("mma.sync.aligned.m16n8k16.row.col.f32.bf16.bf16.f32 "
        "{%0,%1,%2,%3}, {%4,%5,%6,%7}, {%8,%9}, {%0,%1,%2,%3};"
        : "+f"(c[0]), "+f"(c[1]), "+f"(c[2]), "+f"(c[3])
        : "r"(a[0]), "r"(a[1]), "r"(a[2]), "r"(a[3]), "r"(b0), "r"(b1));
}
__device__ __forceinline__ unsigned long long pack2(float x, float y) {
    unsigned long long r;
    asm("mov.b64 %0, {%1, %2};" : "=l"(r) : "f"(x), "f"(y));
    return r;
}
__device__ __forceinline__ void unpack2(unsigned long long v, float& x, float& y) {
    asm("mov.b64 {%0, %1}, %2;" : "=f"(x), "=f"(y) : "l"(v));
}
__device__ __forceinline__ void ffma2(unsigned long long& c, unsigned long long a, unsigned long long b) {
    asm("fma.rn.f32x2 %0, %1, %2, %0;" : "+l"(c) : "l"(a), "l"(b));
}
__device__ __forceinline__ unsigned long long lds_u64(uint32_t a) {
    unsigned long long v;
    asm volatile("ld.shared.b64 %0, [%1];" : "=l"(v) : "r"(a));
    return v;
}

// ============================================================================
// prep_w: fp32 weights -> bf16 hi/lo
// ============================================================================
__global__ void prep_w(Params p) {
    const int seg = blockIdx.y;
    const int mod = seg / 3;
    const int Cin = (mod == 1) ? 1280 : 640;
    const size_t offs[12] = {0, 409600, 819200, 1228800, 2048000, 2867200,
                             3686400, 4096000, 4505600, 4915200, 5324800, 5734400};
    const float* __restrict__ w = p.w[mod * 6 + (seg % 3)];
    const size_t off = offs[seg];
    const size_t n = (size_t)640 * Cin;
    for (size_t i = (size_t)blockIdx.x * blockDim.x + threadIdx.x; i < n; i += (size_t)gridDim.x * blockDim.x) {
        float v = w[i];
        __nv_bfloat16 h = __float2bfloat16(v);
        g_w_hi[off + i] = h;
        g_w_lo[off + i] = __float2bfloat16(v - __bfloat162float(h));
    }
}

// ============================================================================
// prep_x: x[b][C=3200][L=100] fp32 -> XT[b][l][c] bf16 hi/lo
// ============================================================================
__global__ void prep_x(const float* __restrict__ x) {
    __shared__ float t[32][33];
    const int b = blockIdx.z, ct = blockIdx.x, lt = blockIdx.y;
    const int tx = threadIdx.x, ty = threadIdx.y;
    const float* xb = x + (size_t)b * 320000;
    const int l = lt * 32 + tx;
    #pragma unroll
    for (int j = 0; j < 4; j++) {
        int c = ct * 32 + ty + j * 8;
        t[ty + j * 8][tx] = (l < 100) ? xb[(size_t)c * 100 + l] : 0.0f;
    }
    __syncthreads();
    const int c_out = ct * 32 + tx;
    const size_t xtb = (size_t)b * 320000;
    #pragma unroll
    for (int j = 0; j < 4; j++) {
        int lo_ = lt * 32 + ty + j * 8;
        if (lo_ < 100) {
            float v = t[tx][ty + j * 8];
            __nv_bfloat16 h = __float2bfloat16(v);
            size_t o = xtb + (size_t)lo_ * 3200 + c_out;
            g_xt_hi[o] = h;
            g_xt_lo[o] = __float2bfloat16(v - __bfloat162float(h));
        }
    }
}

// ============================================================================
// qkv_mma: REVERTED to the R9 (best, 3504us) version — 8 warps x 13 n8-tiles,
// ldmatrix loads, interleaved MMA stream, cp.async double buffer.
// ============================================================================
#define STAGE  37120u
#define OFF_AH 0u
#define OFF_AL 10240u
#define OFF_BH 20480u
#define OFF_BL 28800u

__global__ __launch_bounds__(256, 2) void qkv_mma(Params p) {
    extern __shared__ __align__(16) char smem_raw[];
    const uint32_t sb = smem_to_u32(smem_raw);

    const int tid = threadIdx.x;
    int bid = blockIdx.x;
    const int mtile = bid % 5; bid /= 5;
    const int proj  = bid % 3; bid /= 3;
    const int mod   = bid & 3;
    const int b     = bid >> 2;

    const int Cin = (mod == 1) ? 1280 : 640;
    const int nch = Cin >> 5;
    const int mbase = mtile * 128;

    const size_t offs[12] = {0, 409600, 819200, 1228800, 2048000, 2867200,
                             3686400, 4096000, 4505600, 4915200, 5324800, 5734400};
    const int c0m_tab[4] = {2560, 640, 1920, 0};
    const size_t woff = offs[mod * 3 + proj];
    const size_t xoff = (size_t)b * 320000 + c0m_tab[mod];
    const float* __restrict__ bias = p.w[mod * 6 + 3 + proj];
    float* __restrict__ O = g_scr + ((((size_t)b * 4 + mod) * 3 + proj) * 640 + mbase) * 100;

    const __nv_bfloat16* __restrict__ Wh = g_w_hi + woff;
    const __nv_bfloat16* __restrict__ Wl = g_w_lo + woff;
    const __nv_bfloat16* __restrict__ Xh = g_xt_hi + xoff;
    const __nv_bfloat16* __restrict__ Xl = g_xt_lo + xoff;

    for (int idx = tid; idx < 320; idx += 256) {
        int st = idx / 160, rest = idx % 160;
        int buf = rest / 80, r2 = rest % 80;
        uint32_t a = sb + (uint32_t)st * STAGE + (buf ? OFF_BL : OFF_BH)
                   + (uint32_t)(100 + r2 / 20) * 80 + (uint32_t)(r2 % 20) * 4;
        asm volatile("st.shared.b32 [%0], %1;" :: "r"(a), "r"(0) : "memory");
    }

    auto issue_chunk = [&](int st, int c) {
        const int k0 = c << 5;
        const uint32_t stg = sb + (uint32_t)st * STAGE;
        for (int idx = tid; idx < 1824; idx += 256) {
            const __nv_bfloat16* src;
            uint32_t dst;
            if (idx < 1024) {
                int buf = idx >> 9, r = (idx >> 2) & 127, seg = idx & 3;
                src = (buf ? Wl : Wh) + (size_t)(mbase + r) * Cin + k0 + seg * 8;
                dst = stg + (buf ? OFF_AL : OFF_AH) + (uint32_t)r * 80 + (uint32_t)seg * 16;
            } else {
                int j = idx - 1024;
                int n = j >> 3, rem = j & 7;
                int buf = rem >> 2, seg = rem & 3;
                src = (buf ? Xl : Xh) + (size_t)n * 3200 + k0 + seg * 8;
                dst = stg + (buf ? OFF_BL : OFF_BH) + (uint32_t)n * 80 + (uint32_t)seg * 16;
            }
            asm volatile("cp.async.cg.shared.global [%0], [%1], 16;" :: "r"(dst), "l"(src) : "memory");
        }
        asm volatile("cp.async.commit_group;" ::: "memory");
    };

    const int w = tid >> 5, lane = tid & 31;
    const int rloc = w * 16 + (lane >> 2);
    const int qd = lane & 3;

    const uint32_t aoff = (uint32_t)(w * 16 + (lane & 15)) * 80 + (uint32_t)(lane >> 4) * 16;
    const uint32_t b4off = (uint32_t)(((lane >> 4) * 8) + (lane & 7)) * 80 + (uint32_t)((lane >> 3) & 1) * 16;
    const uint32_t b2off = (uint32_t)(lane & 7) * 80 + (uint32_t)((lane >> 3) & 1) * 16;

    float acc[13][4];
    #pragma unroll
    for (int t = 0; t < 13; t++)
        #pragma unroll
        for (int i = 0; i < 4; i++) acc[t][i] = 0.0f;

    issue_chunk(0, 0);

    for (int c = 0; c < nch; c++) {
        const int s = c & 1;
        if (c + 1 < nch) {
            issue_chunk(s ^ 1, c + 1);
            asm volatile("cp.async.wait_group 1;" ::: "memory");
        } else {
            asm volatile("cp.async.wait_group 0;" ::: "memory");
        }
        __syncthreads();

        const uint32_t stg = sb + (uint32_t)s * STAGE;
        const uint32_t aAh = stg + OFF_AH + aoff;
        const uint32_t aAl = stg + OFF_AL + aoff;
        const uint32_t aBh4 = stg + OFF_BH + b4off;
        const uint32_t aBl4 = stg + OFF_BL + b4off;
        const uint32_t aBh2 = stg + OFF_BH + 7680u + b2off;
        const uint32_t aBl2 = stg + OFF_BL + 7680u + b2off;

        #pragma unroll
        for (int s16 = 0; s16 < 2; s16++) {
            const uint32_t ko = (uint32_t)s16 * 32;
            uint32_t ah[4], al[4];
            ldsm4(ah, aAh + ko);
            ldsm4(al, aAl + ko);
            #pragma unroll
            for (int pr = 0; pr < 6; pr++) {
                uint32_t bh[4], bl[4];
                ldsm4(bh, aBh4 + (uint32_t)pr * 1280 + ko);
                ldsm4(bl, aBl4 + (uint32_t)pr * 1280 + ko);
                mma16816(acc[2 * pr],     ah, bh[0], bh[1]);
                mma16816(acc[2 * pr + 1], ah, bh[2], bh[3]);
                mma16816(acc[2 * pr],     ah, bl[0], bl[1]);
                mma16816(acc[2 * pr + 1], ah, bl[2], bl[3]);
                mma16816(acc[2 * pr],     al, bh[0], bh[1]);
                mma16816(acc[2 * pr + 1], al, bh[2], bh[3]);
            }
            {
                uint32_t bh[2], bl[2];
                ldsm2(bh, aBh2 + ko);
                ldsm2(bl, aBl2 + ko);
                mma16816(acc[12], ah, bh[0], bh[1]);
                mma16816(acc[12], ah, bl[0], bl[1]);
                mma16816(acc[12], al, bh[0], bh[1]);
            }
        }
        __syncthreads();
    }

    const float bv0 = bias[mbase + rloc];
    const float bv1 = bias[mbase + rloc + 8];
    float* o0 = O + (size_t)rloc * 100;
    float* o1 = o0 + 800;
    #pragma unroll
    for (int t = 0; t < 13; t++) {
        int col = t * 8 + qd * 2;
        if (col < 100) {
            float2 v0 = make_float2(acc[t][0] + bv0, acc[t][1] + bv0);
            float2 v1 = make_float2(acc[t][2] + bv1, acc[t][3] + bv1);
            *(float2*)(o0 + col) = v0;
            *(float2*)(o1 + col) = v1;
        }
    }
}

// ============================================================================
// Pass 2: attention v5.  One CTA per (b,mod), 256 threads, 4 CTAs/SM target.
// Smem (words): Pt[100][100] @0 | U @10000 (Qc/Kc k-chunk16 = 3328w,
//   aliased Vc[40][100] = 4000w over U+part) | part @13328 | row @14328.
// Total 14428 words = 57712 B.  __launch_bounds__(256,4) caps regs at 64.
// ============================================================================
#define PT_OFF   0
#define U_OFF    10000
#define KC_OFF   1664
#define PART_OFF 13328
#define ROW_OFF  14328
#define ATTN_SMEM 57712

__global__ __launch_bounds__(256, 4) void attn_kernel(float* __restrict__ out) {
    extern __shared__ __align__(16) float sm[];
    const int tid = threadIdx.x;
    const int bm = blockIdx.x;           // b*4 + mod
    const int mod = bm & 3, b = bm >> 2;

    const float* __restrict__ Q = g_scr + (size_t)bm * 192000;
    const float* __restrict__ K = Q + 64000;
    const float* __restrict__ V = Q + 128000;
    float* __restrict__ O = out + ((size_t)mod * NB + b) * 64000;

    float* Pt   = sm + PT_OFF;           // [m][l], stride 100
    float* U    = sm + U_OFF;            // Qc/Kc stride 104; Vc stride 100
    float* part = sm + PART_OFF;         // [100][10]
    float* row  = sm + ROW_OFF;          // [100]
    const uint32_t u_b = smem_to_u32(U);
    const uint32_t pt_b = smem_to_u32(Pt);

    // ---- Phase A: S[100,100] = Q^T K, k-chunks of 16 ----
    const bool act = tid < 250;
    const int lg = tid % 25;             // l set {lg, lg+25, lg+50, lg+75}
    const int mg = tid / 25;             // 0..9 active
    const int m0 = mg * 10;

    unsigned long long acc[4][5];
    #pragma unroll
    for (int t = 0; t < 4; t++)
        #pragma unroll
        for (int j = 0; j < 5; j++) acc[t][j] = 0ULL;

    for (int c0 = 0; c0 < 640; c0 += 16) {
        for (int idx = tid; idx < 800; idx += 256) {
            int which = idx >= 400;
            int i2 = idx - which * 400;
            int rw = i2 / 25, c4 = (i2 % 25) * 4;
            const float* src = (which ? K : Q) + (size_t)(c0 + rw) * 100 + c4;
            *(float4*)(U + which * KC_OFF + rw * 104 + c4) = *(const float4*)src;
        }
        __syncthreads();
        if (act) {
            #pragma unroll 2
            for (int kk = 0; kk < 16; kk++) {
                const float* qrow = U + kk * 104;
                unsigned long long qd_[4];
                #pragma unroll
                for (int t = 0; t < 4; t++) {
                    float qv = qrow[lg + 25 * t];
                    qd_[t] = pack2(qv, qv);
                }
                const uint32_t kb = u_b + (uint32_t)(KC_OFF + kk * 104 + m0) * 4;
                #pragma unroll
                for (int j = 0; j < 5; j++) {
                    unsigned long long kv = lds_u64(kb + (uint32_t)j * 8);
                    ffma2(acc[0][j], qd_[0], kv);
                    ffma2(acc[1][j], qd_[1], kv);
                    ffma2(acc[2][j], qd_[2], kv);
                    ffma2(acc[3][j], qd_[3], kv);
                }
            }
        }
        __syncthreads();
    }

    // ---- Softmax (register-resident S) ----
    if (act) {
        #pragma unroll
        for (int t = 0; t < 4; t++) {
            float mx = -3.4e38f;
            #pragma unroll
            for (int j = 0; j < 5; j++) {
                float lo, hi;
                unpack2(acc[t][j], lo, hi);
                mx = fmaxf(mx, fmaxf(lo, hi));
            }
            part[(lg + 25 * t) * 10 + mg] = mx;
        }
    }
    __syncthreads();
    if (tid < 100) {
        float m = -3.4e38f;
        #pragma unroll
        for (int g = 0; g < 10; g++) m = fmaxf(m, part[tid * 10 + g]);
        row[tid] = m;
    }
    __syncthreads();
    if (act) {
        #pragma unroll
        for (int t = 0; t < 4; t++) {
            float mr = row[lg + 25 * t];
            float s = 0.0f;
            #pragma unroll
            for (int j = 0; j < 5; j++) {
                float lo, hi;
                unpack2(acc[t][j], lo, hi);
                float e0 = __expf(lo - mr), e1 = __expf(hi - mr);
                s += e0 + e1;
                acc[t][j] = pack2(e0, e1);
            }
            part[(lg + 25 * t) * 10 + mg] = s;
        }
    }
    __syncthreads();
    if (tid < 100) {
        float s = 0.0f;
        #pragma unroll
        for (int g = 0; g < 10; g++) s += part[tid * 10 + g];
        row[tid] = 1.0f / s;
    }
    __syncthreads();
    if (act) {
        #pragma unroll
        for (int t = 0; t < 4; t++) {
            int l = lg + 25 * t;
            float inv = row[l];
            #pragma unroll
            for (int j = 0; j < 5; j++) {
                float lo, hi;
                unpack2(acc[t][j], lo, hi);
                int m = m0 + 2 * j;
                Pt[m * 100 + l]       = lo * inv;
                Pt[(m + 1) * 100 + l] = hi * inv;
            }
        }
    }

    // ---- Phase C: O[640,100] = V @ P^T, chunks of 40 c-rows ----
    const int cgC = tid % 10, igC = tid / 10;   // igC 0..25, active < 25
    const bool actC = igC < 25;
    const int i0 = igC * 4;

    for (int chunk = 0; chunk < 16; chunk++) {
        __syncthreads();                         // softmax done / prior Vc consumers done
        for (int idx = tid; idx < 1000; idx += 256) {
            int rw = idx / 25, c4 = (idx % 25) * 4;
            *(float4*)(U + rw * 100 + c4) =
                *(const float4*)(V + (size_t)(chunk * 40 + rw) * 100 + c4);
        }
        __syncthreads();
        if (actC) {
            unsigned long long pacc[4][2];
            #pragma unroll
            for (int u = 0; u < 4; u++) { pacc[u][0] = 0ULL; pacc[u][1] = 0ULL; }
            const uint32_t pb = pt_b + (uint32_t)i0 * 4;
            #pragma unroll 4
            for (int j = 0; j < 100; j++) {
                unsigned long long pp0 = lds_u64(pb + (uint32_t)j * 400);
                unsigned long long pp1 = lds_u64(pb + (uint32_t)j * 400 + 8);
                #pragma unroll
                for (int u = 0; u < 4; u++) {
                    float vv = U[(cgC + 10 * u) * 100 + j];
                    unsigned long long vd = pack2(vv, vv);
                    ffma2(pacc[u][0], vd, pp0);
                    ffma2(pacc[u][1], vd, pp1);
                }
            }
            #pragma unroll
            for (int u = 0; u < 4; u++) {
                int c_ = chunk * 40 + cgC + 10 * u;
                float* orow = O + (size_t)c_ * 100 + i0;
                float a0, a1, a2, a3;
                unpack2(pacc[u][0], a0, a1);
                unpack2(pacc[u][1], a2, a3);
                *(float4*)orow = make_float4(a0, a1, a2, a3);
            }
        }
    }
}

extern "C" void kernel_launch(void* const* d_in, const int* in_sizes, int n_in,
                              void* d_out, int out_size) {
    const float* x = (const float*)d_in[0];
    Params p;
    for (int i = 0; i < 24; i++) p.w[i] = (const float*)d_in[1 + i];

    prep_w<<<dim3(800, 12), 256>>>(p);
    prep_x<<<dim3(100, 4, 256), dim3(32, 8)>>>(x);

    cudaFuncSetAttribute(qkv_mma, cudaFuncAttributeMaxDynamicSharedMemorySize, 74240);
    qkv_mma<<<15360, 256, 74240>>>(p);

    cudaFuncSetAttribute(attn_kernel, cudaFuncAttributeMaxDynamicSharedMemorySize, ATTN_SMEM);
    attn_kernel<<<1024, 256, ATTN_SMEM>>>((float*)d_out);
}